// round 12
// baseline (speedup 1.0000x reference)
#include <cuda_runtime.h>
#include <cstdint>

#define D 128
#define C 32
#define LSEQ 4096
#define BH 32
#define NCHUNK 128              // chunks per (b,h)
#define NC_TOTAL 4096           // total chunks
#define ASTR 36                 // 32x32 matrix row stride (pad 4, 16B-aligned rows)
#define RSTR 132                // 32x128 chunk row stride (pad 4, keeps 16B align)
#define KSTR 128                // swizzled k tile row stride (XOR swizzle, no pad)
#define VSLICE 32               // dv slice width per scan CTA
#define NSPLIT 4                // dv splits

// Scratch (allocation-free rule: __device__ globals)
__device__ float g_qn[BH * LSEQ * D];
__device__ float g_kn[BH * LSEQ * D];
__device__ float g_w [BH * LSEQ * D];
__device__ float g_u [BH * LSEQ * D];
__device__ float g_attn[NC_TOTAL * C * C];

// ---------------- packed f32x2 helpers (FFMA2 path, sm_100+) ----------------
__device__ __forceinline__ unsigned long long pk2(float v) {
    unsigned long long r;
    asm("mov.b64 %0, {%1, %1};" : "=l"(r) : "f"(v));
    return r;
}
__device__ __forceinline__ unsigned long long pkf(float lo, float hi) {
    unsigned long long r;
    asm("mov.b64 %0, {%1, %2};" : "=l"(r) : "f"(lo), "f"(hi));
    return r;
}
__device__ __forceinline__ void fma2(unsigned long long& a,
                                     unsigned long long b, unsigned long long c) {
    asm("fma.rn.f32x2 %0, %1, %2, %0;" : "+l"(a) : "l"(b), "l"(c));
}
__device__ __forceinline__ float2 up2(unsigned long long a) {
    float2 f;
    asm("mov.b64 {%0, %1}, %2;" : "=f"(f.x), "=f"(f.y) : "l"(a));
    return f;
}
__device__ __forceinline__ float hadd2(unsigned long long a) {
    float2 f = up2(a); return f.x + f.y;
}
__device__ __forceinline__ void cpa16(uint32_t s, const float* g) {
    asm volatile("cp.async.cg.shared.global [%0], [%1], 16;" :: "r"(s), "l"(g));
}

// ---------------------------------------------------------------------------
// Kernel A: per-chunk preprocessing. (unchanged from R11)
// ---------------------------------------------------------------------------
__global__ void __launch_bounds__(256, 2) prep_kernel(
    const float* __restrict__ q, const float* __restrict__ k,
    const float* __restrict__ v, const float* __restrict__ beta)
{
    extern __shared__ float s[];
    float* sqn = s;                       // 32 x RSTR
    float* skn = sqn + C * RSTR;          // 32 x KSTR (XOR-swizzled chunks)
    float* skb = skn + C * KSTR;          // 32 x RSTR
    float* sv  = skb + C * RSTR;          // 32 x RSTR
    float* sA  = sv  + C * RSTR;          // 32 x ASTR
    float* sP  = sA  + C * ASTR;          // 16 x 17 Schur temp

    const int nc  = blockIdx.x;
    const int t   = threadIdx.x;
    const int w   = t >> 5;
    const int lid = t & 31;
    const size_t base = (size_t)nc * (C * D);

    // ---- Phase 1: normalize + scale ----
    #pragma unroll
    for (int rr = 0; rr < 4; rr++) {
        const int r = w * 4 + rr;
        const float bet = __ldg(beta + (size_t)nc * C + r);
        float4 q4 = *(const float4*)(q + base + r * D + lid * 4);
        float4 k4 = *(const float4*)(k + base + r * D + lid * 4);
        float4 v4 = *(const float4*)(v + base + r * D + lid * 4);
        float qs = q4.x*q4.x + q4.y*q4.y + q4.z*q4.z + q4.w*q4.w;
        float ks = k4.x*k4.x + k4.y*k4.y + k4.z*k4.z + k4.w*k4.w;
        #pragma unroll
        for (int o = 16; o > 0; o >>= 1) {
            qs += __shfl_xor_sync(0xffffffffu, qs, o);
            ks += __shfl_xor_sync(0xffffffffu, ks, o);
        }
        const float qr = rsqrtf(qs + 1e-6f);
        const float kr = rsqrtf(ks + 1e-6f);
        float4 qn = make_float4(q4.x*qr, q4.y*qr, q4.z*qr, q4.w*qr);
        float4 kn = make_float4(k4.x*kr, k4.y*kr, k4.z*kr, k4.w*kr);
        float4 kb = make_float4(kn.x*bet, kn.y*bet, kn.z*bet, kn.w*bet);
        float4 vb = make_float4(v4.x*bet, v4.y*bet, v4.z*bet, v4.w*bet);
        *(float4*)(sqn + r * RSTR + lid * 4) = qn;
        *(float4*)(skn + r * KSTR + ((lid ^ (r & 7)) << 2)) = kn;
        *(float4*)(skb + r * RSTR + lid * 4) = kb;
        *(float4*)(sv  + r * RSTR + lid * 4) = vb;
        *(float4*)(g_qn + base + r * D + lid * 4) = qn;
        *(float4*)(g_kn + base + r * D + lid * 4) = kn;
    }
    __syncthreads();

    // ---- Phase 2: A (strict-lower, negated) and attn (lower incl diag) ----
    {
        const int j  = lid;
        const int i0 = w * 4;
        const int jx = (j & 7);
        unsigned long long A0=0,A1=0,A2=0,A3=0,T0=0,T1=0,T2=0,T3=0;
        const float* kjp = skn + j * KSTR;
        const float* b0p = skb + (i0+0) * RSTR;
        const float* b1p = skb + (i0+1) * RSTR;
        const float* b2p = skb + (i0+2) * RSTR;
        const float* b3p = skb + (i0+3) * RSTR;
        const float* q0p = sqn + (i0+0) * RSTR;
        const float* q1p = sqn + (i0+1) * RSTR;
        const float* q2p = sqn + (i0+2) * RSTR;
        const float* q3p = sqn + (i0+3) * RSTR;
        #pragma unroll 4
        for (int d = 0; d < D; d += 4) {
            ulonglong2 kj = *(const ulonglong2*)(kjp + ((((d >> 2) ^ jx)) << 2));
            ulonglong2 b0 = *(const ulonglong2*)(b0p + d);
            ulonglong2 b1 = *(const ulonglong2*)(b1p + d);
            ulonglong2 b2 = *(const ulonglong2*)(b2p + d);
            ulonglong2 b3 = *(const ulonglong2*)(b3p + d);
            fma2(A0, b0.x, kj.x); fma2(A0, b0.y, kj.y);
            fma2(A1, b1.x, kj.x); fma2(A1, b1.y, kj.y);
            fma2(A2, b2.x, kj.x); fma2(A2, b2.y, kj.y);
            fma2(A3, b3.x, kj.x); fma2(A3, b3.y, kj.y);
            ulonglong2 c0 = *(const ulonglong2*)(q0p + d);
            ulonglong2 c1 = *(const ulonglong2*)(q1p + d);
            ulonglong2 c2 = *(const ulonglong2*)(q2p + d);
            ulonglong2 c3 = *(const ulonglong2*)(q3p + d);
            fma2(T0, c0.x, kj.x); fma2(T0, c0.y, kj.y);
            fma2(T1, c1.x, kj.x); fma2(T1, c1.y, kj.y);
            fma2(T2, c2.x, kj.x); fma2(T2, c2.y, kj.y);
            fma2(T3, c3.x, kj.x); fma2(T3, c3.y, kj.y);
        }
        const float a0 = hadd2(A0), a1 = hadd2(A1), a2 = hadd2(A2), a3 = hadd2(A3);
        const float t0 = hadd2(T0), t1 = hadd2(T1), t2 = hadd2(T2), t3 = hadd2(T3);
        float* ga = g_attn + (size_t)nc * (C * C);
        sA[(i0+0)*ASTR + j] = (j < i0+0) ? -a0 : 0.f;
        sA[(i0+1)*ASTR + j] = (j < i0+1) ? -a1 : 0.f;
        sA[(i0+2)*ASTR + j] = (j < i0+2) ? -a2 : 0.f;
        sA[(i0+3)*ASTR + j] = (j < i0+3) ? -a3 : 0.f;
        ga[(i0+0)*C + j] = (j <= i0+0) ? t0 : 0.f;
        ga[(i0+1)*C + j] = (j <= i0+1) ? t1 : 0.f;
        ga[(i0+2)*C + j] = (j <= i0+2) ? t2 : 0.f;
        ga[(i0+3)*C + j] = (j <= i0+3) ? t3 : 0.f;
    }
    __syncthreads();

    // ---- Phase 3a: two concurrent 16x16 substitutions (warps 0 & 1) ----
    if (w < 2) {
        const int b0 = w * 16;
        const int j  = lid & 15;
        for (int i = 1; i < 16; i++) {
            float acc = 0.f;
            for (int kk = j + 1; kk < i; kk++)
                acc += sA[(b0+i)*ASTR + b0+kk] * sA[(b0+kk)*ASTR + b0+j];
            __syncwarp();
            if (lid < 16 && j < i) sA[(b0+i)*ASTR + b0+j] += acc;
            __syncwarp();
        }
        if (lid < 16) sA[(b0+j)*ASTR + b0+j] = 1.0f;
    }
    __syncthreads();

    // ---- Phase 3b: Schur combine  X21 = X22 * A21 * X11 ----
    {
        const int r = t >> 4;
        const int cc = t & 15;
        float acc = 0.f;
        #pragma unroll 4
        for (int e = 0; e < 16; e++)
            acc += sA[(16+r)*ASTR + e] * sA[e*ASTR + cc];
        sP[r * 17 + cc] = acc;
        __syncthreads();
        float acc2 = 0.f;
        #pragma unroll 4
        for (int e = 0; e < 16; e++)
            acc2 += sA[(16+r)*ASTR + 16+e] * sP[e * 17 + cc];
        sA[(16+r)*ASTR + cc] = acc2;
    }
    __syncthreads();

    // ---- Phase 4: u = inv@v , w = inv@kb ----
    {
        const int i  = t >> 3;
        const int dl = (t & 7) * 4;
        #pragma unroll
        for (int db = 0; db < 4; db++) {
            const int d = db * 32 + dl;
            unsigned long long au01=0, au23=0, aw01=0, aw23=0;
            #pragma unroll 4
            for (int j0 = 0; j0 < C; j0 += 4) {
                float4 a4 = *(const float4*)(sA + i*ASTR + j0);
                #pragma unroll
                for (int jj = 0; jj < 4; jj++) {
                    const float av = (&a4.x)[jj];
                    unsigned long long a2 = pk2(av);
                    ulonglong2 v2 = *(const ulonglong2*)(sv  + (j0+jj)*RSTR + d);
                    ulonglong2 b2 = *(const ulonglong2*)(skb + (j0+jj)*RSTR + d);
                    fma2(au01, a2, v2.x); fma2(au23, a2, v2.y);
                    fma2(aw01, a2, b2.x); fma2(aw23, a2, b2.y);
                }
            }
            float2 l, h;
            l = up2(au01); h = up2(au23);
            *(float4*)(g_u + base + i*D + d) = make_float4(l.x, l.y, h.x, h.y);
            l = up2(aw01); h = up2(aw23);
            *(float4*)(g_w + base + i*D + d) = make_float4(l.x, l.y, h.x, h.y);
        }
    }
}

// ---------------------------------------------------------------------------
// Scan kernel: 512 threads, S traffic held at R10 level.
// Phase-2 thread = (v4 x 4-row-block x d-sixteenth). Lane bit 3 carries the
// low d-split bit -> shfl.bfly(8) reduces pairs; 8 partial matrices in smem
// (indexed by high d-split = warp>>2). Phase 3 (t>=256) and phase 4 (t<256)
// run concurrently.
// ---------------------------------------------------------------------------
#define SBUF (3 * C * RSTR + 2 * C * ASTR)   // q,k,w tiles + u0 + attn per buffer
#define PMAT (C * ASTR)                       // one 32x32 partial matrix

__device__ __forceinline__ void prefetch_chunk(
    uint32_t smb, int ci, int t, int v0,
    const float* gq, const float* gk, const float* gw,
    const float* gu, const float* ga)
{
    const int w   = t >> 5;
    const int lid = t & 31;
    const size_t cb = (size_t)ci * (C * D);
    const uint32_t OK  = (uint32_t)(C * RSTR) * 4u;
    const uint32_t OW  = 2u * OK;
    const uint32_t OU0 = 3u * OK;
    const uint32_t OAT = OU0 + (uint32_t)(C * ASTR) * 4u;
    #pragma unroll
    for (int rr = 0; rr < 2; rr++) {
        const int r = w * 2 + rr;
        const uint32_t off = (uint32_t)(r * RSTR + lid * 4) * 4u;
        cpa16(smb +      off, gq + cb + r * D + lid * 4);
        cpa16(smb + OK + off, gk + cb + r * D + lid * 4);
        cpa16(smb + OW + off, gw + cb + r * D + lid * 4);
    }
    if (t < 256) {
        const int c  = t >> 3;
        const int v4 = (t & 7) * 4;
        cpa16(smb + OU0 + (uint32_t)(c * ASTR + v4) * 4u, gu + cb + c * D + v0 + v4);
        cpa16(smb + OAT + (uint32_t)(c * ASTR + v4) * 4u,
              ga + (size_t)ci * (C * C) + c * C + v4);
    }
    asm volatile("cp.async.commit_group;");
}

__global__ void __launch_bounds__(512, 1) scan_kernel(float* __restrict__ out)
{
    extern __shared__ float s[];
    float* sS  = s;                         // 128 x VSLICE
    float* sb0 = sS + D * VSLICE;
    float* sb1 = sb0 + SBUF;
    float* sui = sb1 + SBUF;                // 32 x ASTR
    float* sPQ = sui + C * ASTR;            // 32 x ASTR (final q@S)
    float* sPP = sPQ + C * ASTR;            // 8 x PMAT partial matrices (4 U, 4 Q)

    const int bh  = blockIdx.y;
    const int v0  = blockIdx.x * VSLICE;
    const int t   = threadIdx.x;
    const int w   = t >> 5;
    // phase-2 mapping: lane = v4(3b) | dqlo(1b) | r0lo(1b); warp = r0hi(2b) | dqhi(2b)
    const int v4    = (t & 7) * 4;
    const int dqlo  = (t >> 3) & 1;
    const int r0    = (((t >> 4) & 1) + (w & 3) * 2) * 4;   // 8 blocks of 4 rows
    const int dqhi  = w >> 2;                               // 0..3
    const int dbeg  = (dqhi * 2 + dqlo) * 16;               // d in [dbeg, dbeg+16)
    // phase-3/4 and combine mapping (t < 256 半; phase3 uses t-256)
    const int c   = (t & 255) >> 3;
    const int cv4 = (t & 7) * 4;

    // zero S (512 threads x 2 float4 = 4096 floats)
    #pragma unroll
    for (int rr = 0; rr < 2; rr++)
        *(float4*)(sS + (rr * 512 + t) * 4) = make_float4(0.f, 0.f, 0.f, 0.f);

    const uint32_t smb0 = (uint32_t)__cvta_generic_to_shared(sb0);
    const uint32_t smb1 = (uint32_t)__cvta_generic_to_shared(sb1);

    const size_t bhb = (size_t)bh * LSEQ * D;
    const float* gq = g_qn + bhb;
    const float* gk = g_kn + bhb;
    const float* gw = g_w  + bhb;
    const float* gu = g_u  + bhb;
    const float* ga = g_attn + (size_t)bh * NCHUNK * (C * C);

    prefetch_chunk(smb0, 0, t, v0, gq, gk, gw, gu, ga);

    const unsigned long long ONE2 = pk2(1.0f);

    for (int ci = 0; ci < NCHUNK; ci++) {
        float* B = (ci & 1) ? sb1 : sb0;
        const uint32_t smn = (ci & 1) ? smb0 : smb1;
        const float* sq  = B;
        const float* sk  = B + C * RSTR;
        const float* sw  = B + 2 * C * RSTR;
        const float* su0 = B + 3 * C * RSTR;
        const float* sat = su0 + C * ASTR;

        asm volatile("cp.async.wait_group 0;");
        __syncthreads();                    // tiles ready + prev S update done

        const int cn = (ci + 1 < NCHUNK) ? ci + 1 : ci;
        prefetch_chunk(smn, cn, t, v0, gq, gk, gw, gu, ga);

        // ---- phase 2: 16-d GEMV slice, 4 rows/thread ----
        unsigned long long aU[4][2], aQ[4][2];
        #pragma unroll
        for (int r = 0; r < 4; r++) {
            aU[r][0]=0; aU[r][1]=0; aQ[r][0]=0; aQ[r][1]=0;
        }
        {
            const float* wp = sw + dbeg;
            const float* qp = sq + dbeg;
            const float* Sp = sS + dbeg * VSLICE + v4;
            #pragma unroll
            for (int dg = 0; dg < 16; dg += 4) {
                float4 wv[4], qv[4];
                #pragma unroll
                for (int r = 0; r < 4; r++) {
                    wv[r] = *(const float4*)(wp + (r0 + r) * RSTR + dg);
                    qv[r] = *(const float4*)(qp + (r0 + r) * RSTR + dg);
                }
                #pragma unroll
                for (int i = 0; i < 4; i++) {
                    ulonglong2 S2 = *(const ulonglong2*)(Sp + (dg + i) * VSLICE);
                    #pragma unroll
                    for (int r = 0; r < 4; r++) {
                        unsigned long long w2 = pk2((&wv[r].x)[i]);
                        unsigned long long q2 = pk2((&qv[r].x)[i]);
                        fma2(aU[r][0], w2, S2.x); fma2(aU[r][1], w2, S2.y);
                        fma2(aQ[r][0], q2, S2.x); fma2(aQ[r][1], q2, S2.y);
                    }
                }
            }
        }
        // ---- reduce dqlo pairs via butterfly shuffle (xor lane bit 3) ----
        #pragma unroll
        for (int r = 0; r < 4; r++) {
            #pragma unroll
            for (int h = 0; h < 2; h++) {
                unsigned long long oU = __shfl_xor_sync(0xffffffffu, aU[r][h], 8);
                unsigned long long oQ = __shfl_xor_sync(0xffffffffu, aQ[r][h], 8);
                fma2(aU[r][h], oU, ONE2);
                fma2(aQ[r][h], oQ, ONE2);
            }
        }
        if (!dqlo) {                        // one lane of each pair stores
            float* PU = sPP + dqhi * PMAT;
            float* PQ = sPP + (4 + dqhi) * PMAT;
            #pragma unroll
            for (int r = 0; r < 4; r++) {
                float2 l, h;
                l = up2(aU[r][0]); h = up2(aU[r][1]);
                *(float4*)(PU + (r0 + r) * ASTR + v4) = make_float4(l.x, l.y, h.x, h.y);
                l = up2(aQ[r][0]); h = up2(aQ[r][1]);
                *(float4*)(PQ + (r0 + r) * ASTR + v4) = make_float4(l.x, l.y, h.x, h.y);
            }
        }
        __syncthreads();

        // ---- combine (t < 256): one (c, cv4) each ----
        if (t < 256) {
            float4 u0 = *(const float4*)(su0 + c * ASTR + cv4);
            float4 aUc = make_float4(0.f,0.f,0.f,0.f);
            float4 aQc = make_float4(0.f,0.f,0.f,0.f);
            #pragma unroll
            for (int p = 0; p < 4; p++) {
                float4 pu = *(const float4*)(sPP + p * PMAT + c * ASTR + cv4);
                float4 pq = *(const float4*)(sPP + (4+p) * PMAT + c * ASTR + cv4);
                aUc.x += pu.x; aUc.y += pu.y; aUc.z += pu.z; aUc.w += pu.w;
                aQc.x += pq.x; aQc.y += pq.y; aQc.z += pq.z; aQc.w += pq.w;
            }
            *(float4*)(sui + c * ASTR + cv4) = make_float4(
                u0.x - aUc.x, u0.y - aUc.y, u0.z - aUc.z, u0.w - aUc.w);
            *(float4*)(sPQ + c * ASTR + cv4) = aQc;
        }
        __syncthreads();

        if (t >= 256) {
            // ---- phase 3 (threads 256..511): out = q@S + attn @ u_i ----
            float4 a0 = *(const float4*)(sPQ + c * ASTR + cv4);
            unsigned long long o01 = pkf(a0.x, a0.y);
            unsigned long long o23 = pkf(a0.z, a0.w);
            #pragma unroll 8
            for (int e = 0; e < C; e++) {
                unsigned long long a2 = pk2(sat[c * ASTR + e]);
                ulonglong2 u2 = *(const ulonglong2*)(sui + e * ASTR + cv4);
                fma2(o01, a2, u2.x); fma2(o23, a2, u2.y);
            }
            float2 l = up2(o01), h = up2(o23);
            *(float4*)(out + bhb + (size_t)ci * (C * D) + c * D + v0 + cv4) =
                make_float4(l.x, l.y, h.x, h.y);
        } else {
            // ---- phase 4 (threads 0..255): S[d,v] += sum_e k[e,d]*u_i[e,v] ----
            unsigned long long A0=0,A1=0,A2=0,A3=0,A4=0,A5=0,A6=0,A7=0;
            #pragma unroll 4
            for (int e = 0; e < C; e++) {
                ulonglong2 u2 = *(const ulonglong2*)(sui + e * ASTR + cv4);
                unsigned long long k0 = pk2(sk[e * RSTR + c]);
                unsigned long long k1 = pk2(sk[e * RSTR + c + 32]);
                unsigned long long k2 = pk2(sk[e * RSTR + c + 64]);
                unsigned long long k3 = pk2(sk[e * RSTR + c + 96]);
                fma2(A0, k0, u2.x); fma2(A1, k0, u2.y);
                fma2(A2, k1, u2.x); fma2(A3, k1, u2.y);
                fma2(A4, k2, u2.x); fma2(A5, k2, u2.y);
                fma2(A6, k3, u2.x); fma2(A7, k3, u2.y);
            }
            float2 l, h;
            float4* p0 = (float4*)(sS + (c      ) * VSLICE + cv4);
            float4* p1 = (float4*)(sS + (c +  32) * VSLICE + cv4);
            float4* p2 = (float4*)(sS + (c +  64) * VSLICE + cv4);
            float4* p3 = (float4*)(sS + (c +  96) * VSLICE + cv4);
            float4 t0 = *p0, t1 = *p1, t2 = *p2, t3 = *p3;
            l = up2(A0); h = up2(A1);
            t0.x += l.x; t0.y += l.y; t0.z += h.x; t0.w += h.y;
            l = up2(A2); h = up2(A3);
            t1.x += l.x; t1.y += l.y; t1.z += h.x; t1.w += h.y;
            l = up2(A4); h = up2(A5);
            t2.x += l.x; t2.y += l.y; t2.z += h.x; t2.w += h.y;
            l = up2(A6); h = up2(A7);
            t3.x += l.x; t3.y += l.y; t3.z += h.x; t3.w += h.y;
            *p0 = t0; *p1 = t1; *p2 = t2; *p3 = t3;
        }
    }
}

// ---------------------------------------------------------------------------
extern "C" void kernel_launch(void* const* d_in, const int* in_sizes, int n_in,
                              void* d_out, int out_size)
{
    const float* q    = (const float*)d_in[0];
    const float* k    = (const float*)d_in[1];
    const float* v    = (const float*)d_in[2];
    const float* beta = (const float*)d_in[3];
    float* out = (float*)d_out;

    const size_t smemA = (size_t)(3 * C * RSTR + C * KSTR + C * ASTR + 16 * 17)
                         * sizeof(float);
    const size_t smemB = (size_t)(D * VSLICE + 2 * SBUF + 2 * C * ASTR + 8 * PMAT)
                         * sizeof(float);

    cudaFuncSetAttribute(prep_kernel, cudaFuncAttributeMaxDynamicSharedMemorySize,
                         (int)smemA);
    cudaFuncSetAttribute(scan_kernel, cudaFuncAttributeMaxDynamicSharedMemorySize,
                         (int)smemB);

    prep_kernel<<<NC_TOTAL, 256, smemA>>>(q, k, v, beta);
    scan_kernel<<<dim3(NSPLIT, BH), 512, smemB>>>(out);
}

// round 13
// speedup vs baseline: 1.0511x; 1.0511x over previous
#include <cuda_runtime.h>
#include <cstdint>

#define D 128
#define C 32
#define LSEQ 4096
#define BH 32
#define NCHUNK 128              // chunks per (b,h)
#define NC_TOTAL 4096           // total chunks
#define ASTR 36                 // 32x32 matrix row stride (pad 4, 16B-aligned rows)
#define RSTR 132                // 32x128 chunk row stride (pad 4, keeps 16B align)
#define KSTR 128                // swizzled k tile row stride (XOR swizzle, no pad)
#define VSLICE 32               // dv slice width per scan CTA
#define NSPLIT 4                // dv splits

// Scratch (allocation-free rule: __device__ globals)
__device__ float g_qn[BH * LSEQ * D];
__device__ float g_kn[BH * LSEQ * D];
__device__ float g_w [BH * LSEQ * D];
__device__ float g_u [BH * LSEQ * D];
__device__ float g_attn[NC_TOTAL * C * C];

// ---------------- packed f32x2 helpers (FFMA2 path, sm_100+) ----------------
__device__ __forceinline__ unsigned long long pk2(float v) {
    unsigned long long r;
    asm("mov.b64 %0, {%1, %1};" : "=l"(r) : "f"(v));
    return r;
}
__device__ __forceinline__ unsigned long long pkf(float lo, float hi) {
    unsigned long long r;
    asm("mov.b64 %0, {%1, %2};" : "=l"(r) : "f"(lo), "f"(hi));
    return r;
}
__device__ __forceinline__ void fma2(unsigned long long& a,
                                     unsigned long long b, unsigned long long c) {
    asm("fma.rn.f32x2 %0, %1, %2, %0;" : "+l"(a) : "l"(b), "l"(c));
}
__device__ __forceinline__ float2 up2(unsigned long long a) {
    float2 f;
    asm("mov.b64 {%0, %1}, %2;" : "=f"(f.x), "=f"(f.y) : "l"(a));
    return f;
}
__device__ __forceinline__ float hadd2(unsigned long long a) {
    float2 f = up2(a); return f.x + f.y;
}
__device__ __forceinline__ void cpa16(uint32_t s, const float* g) {
    asm volatile("cp.async.cg.shared.global [%0], [%1], 16;" :: "r"(s), "l"(g));
}

// ---------------------------------------------------------------------------
// Kernel A: per-chunk preprocessing. R11 logic; occupancy raised to 3 CTAs/SM
// (smem 72.8KB x3 = 218KB < 227KB; regs capped at 84 by launch bounds).
// ---------------------------------------------------------------------------
__global__ void __launch_bounds__(256, 3) prep_kernel(
    const float* __restrict__ q, const float* __restrict__ k,
    const float* __restrict__ v, const float* __restrict__ beta)
{
    extern __shared__ float s[];
    float* sqn = s;                       // 32 x RSTR
    float* skn = sqn + C * RSTR;          // 32 x KSTR (XOR-swizzled chunks)
    float* skb = skn + C * KSTR;          // 32 x RSTR
    float* sv  = skb + C * RSTR;          // 32 x RSTR
    float* sA  = sv  + C * RSTR;          // 32 x ASTR
    float* sP  = sA  + C * ASTR;          // 16 x 17 Schur temp

    const int nc  = blockIdx.x;
    const int t   = threadIdx.x;
    const int w   = t >> 5;
    const int lid = t & 31;
    const size_t base = (size_t)nc * (C * D);

    // ---- Phase 1: normalize + scale ----
    #pragma unroll
    for (int rr = 0; rr < 4; rr++) {
        const int r = w * 4 + rr;
        const float bet = __ldg(beta + (size_t)nc * C + r);
        float4 q4 = *(const float4*)(q + base + r * D + lid * 4);
        float4 k4 = *(const float4*)(k + base + r * D + lid * 4);
        float4 v4 = *(const float4*)(v + base + r * D + lid * 4);
        float qs = q4.x*q4.x + q4.y*q4.y + q4.z*q4.z + q4.w*q4.w;
        float ks = k4.x*k4.x + k4.y*k4.y + k4.z*k4.z + k4.w*k4.w;
        #pragma unroll
        for (int o = 16; o > 0; o >>= 1) {
            qs += __shfl_xor_sync(0xffffffffu, qs, o);
            ks += __shfl_xor_sync(0xffffffffu, ks, o);
        }
        const float qr = rsqrtf(qs + 1e-6f);
        const float kr = rsqrtf(ks + 1e-6f);
        float4 qn = make_float4(q4.x*qr, q4.y*qr, q4.z*qr, q4.w*qr);
        float4 kn = make_float4(k4.x*kr, k4.y*kr, k4.z*kr, k4.w*kr);
        float4 kb = make_float4(kn.x*bet, kn.y*bet, kn.z*bet, kn.w*bet);
        float4 vb = make_float4(v4.x*bet, v4.y*bet, v4.z*bet, v4.w*bet);
        *(float4*)(sqn + r * RSTR + lid * 4) = qn;
        *(float4*)(skn + r * KSTR + ((lid ^ (r & 7)) << 2)) = kn;
        *(float4*)(skb + r * RSTR + lid * 4) = kb;
        *(float4*)(sv  + r * RSTR + lid * 4) = vb;
        *(float4*)(g_qn + base + r * D + lid * 4) = qn;
        *(float4*)(g_kn + base + r * D + lid * 4) = kn;
    }
    __syncthreads();

    // ---- Phase 2: A (strict-lower, negated) and attn (lower incl diag) ----
    {
        const int j  = lid;
        const int i0 = w * 4;
        const int jx = (j & 7);
        unsigned long long A0=0,A1=0,A2=0,A3=0,T0=0,T1=0,T2=0,T3=0;
        const float* kjp = skn + j * KSTR;
        const float* b0p = skb + (i0+0) * RSTR;
        const float* b1p = skb + (i0+1) * RSTR;
        const float* b2p = skb + (i0+2) * RSTR;
        const float* b3p = skb + (i0+3) * RSTR;
        const float* q0p = sqn + (i0+0) * RSTR;
        const float* q1p = sqn + (i0+1) * RSTR;
        const float* q2p = sqn + (i0+2) * RSTR;
        const float* q3p = sqn + (i0+3) * RSTR;
        #pragma unroll 4
        for (int d = 0; d < D; d += 4) {
            ulonglong2 kj = *(const ulonglong2*)(kjp + ((((d >> 2) ^ jx)) << 2));
            ulonglong2 b0 = *(const ulonglong2*)(b0p + d);
            ulonglong2 b1 = *(const ulonglong2*)(b1p + d);
            ulonglong2 b2 = *(const ulonglong2*)(b2p + d);
            ulonglong2 b3 = *(const ulonglong2*)(b3p + d);
            fma2(A0, b0.x, kj.x); fma2(A0, b0.y, kj.y);
            fma2(A1, b1.x, kj.x); fma2(A1, b1.y, kj.y);
            fma2(A2, b2.x, kj.x); fma2(A2, b2.y, kj.y);
            fma2(A3, b3.x, kj.x); fma2(A3, b3.y, kj.y);
            ulonglong2 c0 = *(const ulonglong2*)(q0p + d);
            ulonglong2 c1 = *(const ulonglong2*)(q1p + d);
            ulonglong2 c2 = *(const ulonglong2*)(q2p + d);
            ulonglong2 c3 = *(const ulonglong2*)(q3p + d);
            fma2(T0, c0.x, kj.x); fma2(T0, c0.y, kj.y);
            fma2(T1, c1.x, kj.x); fma2(T1, c1.y, kj.y);
            fma2(T2, c2.x, kj.x); fma2(T2, c2.y, kj.y);
            fma2(T3, c3.x, kj.x); fma2(T3, c3.y, kj.y);
        }
        const float a0 = hadd2(A0), a1 = hadd2(A1), a2 = hadd2(A2), a3 = hadd2(A3);
        const float t0 = hadd2(T0), t1 = hadd2(T1), t2 = hadd2(T2), t3 = hadd2(T3);
        float* ga = g_attn + (size_t)nc * (C * C);
        sA[(i0+0)*ASTR + j] = (j < i0+0) ? -a0 : 0.f;
        sA[(i0+1)*ASTR + j] = (j < i0+1) ? -a1 : 0.f;
        sA[(i0+2)*ASTR + j] = (j < i0+2) ? -a2 : 0.f;
        sA[(i0+3)*ASTR + j] = (j < i0+3) ? -a3 : 0.f;
        ga[(i0+0)*C + j] = (j <= i0+0) ? t0 : 0.f;
        ga[(i0+1)*C + j] = (j <= i0+1) ? t1 : 0.f;
        ga[(i0+2)*C + j] = (j <= i0+2) ? t2 : 0.f;
        ga[(i0+3)*C + j] = (j <= i0+3) ? t3 : 0.f;
    }
    __syncthreads();

    // ---- Phase 3a: two concurrent 16x16 substitutions (warps 0 & 1) ----
    if (w < 2) {
        const int b0 = w * 16;
        const int j  = lid & 15;
        for (int i = 1; i < 16; i++) {
            float acc = 0.f;
            for (int kk = j + 1; kk < i; kk++)
                acc += sA[(b0+i)*ASTR + b0+kk] * sA[(b0+kk)*ASTR + b0+j];
            __syncwarp();
            if (lid < 16 && j < i) sA[(b0+i)*ASTR + b0+j] += acc;
            __syncwarp();
        }
        if (lid < 16) sA[(b0+j)*ASTR + b0+j] = 1.0f;
    }
    __syncthreads();

    // ---- Phase 3b: Schur combine  X21 = X22 * A21 * X11 ----
    {
        const int r = t >> 4;
        const int cc = t & 15;
        float acc = 0.f;
        #pragma unroll 4
        for (int e = 0; e < 16; e++)
            acc += sA[(16+r)*ASTR + e] * sA[e*ASTR + cc];
        sP[r * 17 + cc] = acc;
        __syncthreads();
        float acc2 = 0.f;
        #pragma unroll 4
        for (int e = 0; e < 16; e++)
            acc2 += sA[(16+r)*ASTR + 16+e] * sP[e * 17 + cc];
        sA[(16+r)*ASTR + cc] = acc2;
    }
    __syncthreads();

    // ---- Phase 4: u = inv@v , w = inv@kb ----
    {
        const int i  = t >> 3;
        const int dl = (t & 7) * 4;
        #pragma unroll
        for (int db = 0; db < 4; db++) {
            const int d = db * 32 + dl;
            unsigned long long au01=0, au23=0, aw01=0, aw23=0;
            #pragma unroll 4
            for (int j0 = 0; j0 < C; j0 += 4) {
                float4 a4 = *(const float4*)(sA + i*ASTR + j0);
                #pragma unroll
                for (int jj = 0; jj < 4; jj++) {
                    const float av = (&a4.x)[jj];
                    unsigned long long a2 = pk2(av);
                    ulonglong2 v2 = *(const ulonglong2*)(sv  + (j0+jj)*RSTR + d);
                    ulonglong2 b2 = *(const ulonglong2*)(skb + (j0+jj)*RSTR + d);
                    fma2(au01, a2, v2.x); fma2(au23, a2, v2.y);
                    fma2(aw01, a2, b2.x); fma2(aw23, a2, b2.y);
                }
            }
            float2 l, h;
            l = up2(au01); h = up2(au23);
            *(float4*)(g_u + base + i*D + d) = make_float4(l.x, l.y, h.x, h.y);
            l = up2(aw01); h = up2(aw23);
            *(float4*)(g_w + base + i*D + d) = make_float4(l.x, l.y, h.x, h.y);
        }
    }
}

// ---------------------------------------------------------------------------
// Scan kernel: byte-identical to R11 (best measured scan: 529us).
// 256 threads; phase-2 4-row register tiling + d-quarters; all quarters store
// partials; distributed combine.
// ---------------------------------------------------------------------------
#define SBUF (3 * C * RSTR + 2 * C * ASTR)   // q,k,w tiles + u0 + attn per buffer
#define PMAT (C * ASTR)                       // one 32x32 partial matrix

__device__ __forceinline__ void prefetch_chunk(
    uint32_t smb, int ci, int w, int lid, int c, int v4, int v0,
    const float* gq, const float* gk, const float* gw,
    const float* gu, const float* ga)
{
    const size_t cb = (size_t)ci * (C * D);
    const uint32_t OK  = (uint32_t)(C * RSTR) * 4u;
    const uint32_t OW  = 2u * OK;
    const uint32_t OU0 = 3u * OK;
    const uint32_t OAT = OU0 + (uint32_t)(C * ASTR) * 4u;
    #pragma unroll
    for (int rr = 0; rr < 4; rr++) {
        const int r = w * 4 + rr;
        const uint32_t off = (uint32_t)(r * RSTR + lid * 4) * 4u;
        cpa16(smb +      off, gq + cb + r * D + lid * 4);
        cpa16(smb + OK + off, gk + cb + r * D + lid * 4);
        cpa16(smb + OW + off, gw + cb + r * D + lid * 4);
    }
    cpa16(smb + OU0 + (uint32_t)(c * ASTR + v4) * 4u, gu + cb + c * D + v0 + v4);
    cpa16(smb + OAT + (uint32_t)(c * ASTR + v4) * 4u,
          ga + (size_t)ci * (C * C) + c * C + v4);
    asm volatile("cp.async.commit_group;");
}

__global__ void __launch_bounds__(256, 1) scan_kernel(float* __restrict__ out)
{
    extern __shared__ float s[];
    float* sS  = s;                         // 128 x VSLICE
    float* sb0 = sS + D * VSLICE;
    float* sb1 = sb0 + SBUF;
    float* sui = sb1 + SBUF;                // 32 x ASTR
    float* sPQ = sui + C * ASTR;            // 32 x ASTR (final q@S)
    float* sPP = sPQ + C * ASTR;            // 8 x PMAT partial matrices (4 U, 4 Q)

    const int bh  = blockIdx.y;
    const int v0  = blockIdx.x * VSLICE;
    const int t   = threadIdx.x;
    const int w   = t >> 5;
    const int lid = t & 31;
    const int v4  = (t & 7) * 4;
    const int r0  = ((t >> 3) & 7) * 4;     // rows r0..r0+3
    const int dq  = t >> 6;                 // d quarter 0..3
    const int c   = t >> 3;

    #pragma unroll
    for (int rr = 0; rr < 4; rr++)
        *(float4*)(sS + (rr * 256 + t) * 4) = make_float4(0.f, 0.f, 0.f, 0.f);

    const uint32_t smb0 = (uint32_t)__cvta_generic_to_shared(sb0);
    const uint32_t smb1 = (uint32_t)__cvta_generic_to_shared(sb1);

    const size_t bhb = (size_t)bh * LSEQ * D;
    const float* gq = g_qn + bhb;
    const float* gk = g_kn + bhb;
    const float* gw = g_w  + bhb;
    const float* gu = g_u  + bhb;
    const float* ga = g_attn + (size_t)bh * NCHUNK * (C * C);

    prefetch_chunk(smb0, 0, w, lid, c, v4, v0, gq, gk, gw, gu, ga);

    for (int ci = 0; ci < NCHUNK; ci++) {
        float* B = (ci & 1) ? sb1 : sb0;
        const uint32_t smn = (ci & 1) ? smb0 : smb1;
        const float* sq  = B;
        const float* sk  = B + C * RSTR;
        const float* sw  = B + 2 * C * RSTR;
        const float* su0 = B + 3 * C * RSTR;
        const float* sat = su0 + C * ASTR;

        asm volatile("cp.async.wait_group 0;");
        __syncthreads();                    // tiles ready + prev S update done

        const int cn = (ci + 1 < NCHUNK) ? ci + 1 : ci;
        prefetch_chunk(smn, cn, w, lid, c, v4, v0, gq, gk, gw, gu, ga);

        // ---- phase 2: quarter-d GEMV, 4 rows/thread; ALL quarters store ----
        {
            unsigned long long aU[4][2], aQ[4][2];
            #pragma unroll
            for (int r = 0; r < 4; r++) {
                aU[r][0]=0; aU[r][1]=0; aQ[r][0]=0; aQ[r][1]=0;
            }
            const int dbeg = dq * 32;
            const float* wp = sw + dbeg;
            const float* qp = sq + dbeg;
            const float* Sp = sS + dbeg * VSLICE + v4;
            #pragma unroll 2
            for (int dg = 0; dg < 32; dg += 4) {
                float4 wv[4], qv[4];
                #pragma unroll
                for (int r = 0; r < 4; r++) {
                    wv[r] = *(const float4*)(wp + (r0 + r) * RSTR + dg);
                    qv[r] = *(const float4*)(qp + (r0 + r) * RSTR + dg);
                }
                #pragma unroll
                for (int i = 0; i < 4; i++) {
                    ulonglong2 S2 = *(const ulonglong2*)(Sp + (dg + i) * VSLICE);
                    #pragma unroll
                    for (int r = 0; r < 4; r++) {
                        unsigned long long w2 = pk2((&wv[r].x)[i]);
                        unsigned long long q2 = pk2((&qv[r].x)[i]);
                        fma2(aU[r][0], w2, S2.x); fma2(aU[r][1], w2, S2.y);
                        fma2(aQ[r][0], q2, S2.x); fma2(aQ[r][1], q2, S2.y);
                    }
                }
            }
            float* PU = sPP + dq * PMAT;
            float* PQ = sPP + (4 + dq) * PMAT;
            #pragma unroll
            for (int r = 0; r < 4; r++) {
                float2 l, h;
                l = up2(aU[r][0]); h = up2(aU[r][1]);
                *(float4*)(PU + (r0 + r) * ASTR + v4) = make_float4(l.x, l.y, h.x, h.y);
                l = up2(aQ[r][0]); h = up2(aQ[r][1]);
                *(float4*)(PQ + (r0 + r) * ASTR + v4) = make_float4(l.x, l.y, h.x, h.y);
            }
        }
        __syncthreads();

        // ---- combine (ALL 256 threads): one (c, v4) each ----
        {
            float4 u0 = *(const float4*)(su0 + c * ASTR + v4);
            float4 aU = make_float4(0.f,0.f,0.f,0.f);
            float4 aQ = make_float4(0.f,0.f,0.f,0.f);
            #pragma unroll
            for (int p = 0; p < 4; p++) {
                float4 pu = *(const float4*)(sPP + p * PMAT + c * ASTR + v4);
                float4 pq = *(const float4*)(sPP + (4+p) * PMAT + c * ASTR + v4);
                aU.x += pu.x; aU.y += pu.y; aU.z += pu.z; aU.w += pu.w;
                aQ.x += pq.x; aQ.y += pq.y; aQ.z += pq.z; aQ.w += pq.w;
            }
            *(float4*)(sui + c * ASTR + v4) = make_float4(
                u0.x - aU.x, u0.y - aU.y, u0.z - aU.z, u0.w - aU.w);
            *(float4*)(sPQ + c * ASTR + v4) = aQ;
        }
        __syncthreads();

        // ---- phase 3: out = q@S + attn @ u_i (all 256 threads) ----
        {
            float4 a0 = *(const float4*)(sPQ + c * ASTR + v4);
            unsigned long long o01 = pkf(a0.x, a0.y);
            unsigned long long o23 = pkf(a0.z, a0.w);
            #pragma unroll 8
            for (int e = 0; e < C; e++) {
                unsigned long long a2 = pk2(sat[c * ASTR + e]);
                ulonglong2 u2 = *(const ulonglong2*)(sui + e * ASTR + v4);
                fma2(o01, a2, u2.x); fma2(o23, a2, u2.y);
            }
            float2 l = up2(o01), h = up2(o23);
            *(float4*)(out + bhb + (size_t)ci * (C * D) + c * D + v0 + v4) =
                make_float4(l.x, l.y, h.x, h.y);
        }

        // ---- phase 4: S[d,v] += sum_e k[e,d] * u_i[e,v] ----
        {
            unsigned long long A0=0,A1=0,A2=0,A3=0,A4=0,A5=0,A6=0,A7=0;
            #pragma unroll 4
            for (int e = 0; e < C; e++) {
                ulonglong2 u2 = *(const ulonglong2*)(sui + e * ASTR + v4);
                unsigned long long k0 = pk2(sk[e * RSTR + c]);
                unsigned long long k1 = pk2(sk[e * RSTR + c + 32]);
                unsigned long long k2 = pk2(sk[e * RSTR + c + 64]);
                unsigned long long k3 = pk2(sk[e * RSTR + c + 96]);
                fma2(A0, k0, u2.x); fma2(A1, k0, u2.y);
                fma2(A2, k1, u2.x); fma2(A3, k1, u2.y);
                fma2(A4, k2, u2.x); fma2(A5, k2, u2.y);
                fma2(A6, k3, u2.x); fma2(A7, k3, u2.y);
            }
            float2 l, h;
            float4* p0 = (float4*)(sS + (c      ) * VSLICE + v4);
            float4* p1 = (float4*)(sS + (c +  32) * VSLICE + v4);
            float4* p2 = (float4*)(sS + (c +  64) * VSLICE + v4);
            float4* p3 = (float4*)(sS + (c +  96) * VSLICE + v4);
            float4 t0 = *p0, t1 = *p1, t2 = *p2, t3 = *p3;
            l = up2(A0); h = up2(A1);
            t0.x += l.x; t0.y += l.y; t0.z += h.x; t0.w += h.y;
            l = up2(A2); h = up2(A3);
            t1.x += l.x; t1.y += l.y; t1.z += h.x; t1.w += h.y;
            l = up2(A4); h = up2(A5);
            t2.x += l.x; t2.y += l.y; t2.z += h.x; t2.w += h.y;
            l = up2(A6); h = up2(A7);
            t3.x += l.x; t3.y += l.y; t3.z += h.x; t3.w += h.y;
            *p0 = t0; *p1 = t1; *p2 = t2; *p3 = t3;
        }
    }
}

// ---------------------------------------------------------------------------
extern "C" void kernel_launch(void* const* d_in, const int* in_sizes, int n_in,
                              void* d_out, int out_size)
{
    const float* q    = (const float*)d_in[0];
    const float* k    = (const float*)d_in[1];
    const float* v    = (const float*)d_in[2];
    const float* beta = (const float*)d_in[3];
    float* out = (float*)d_out;

    const size_t smemA = (size_t)(3 * C * RSTR + C * KSTR + C * ASTR + 16 * 17)
                         * sizeof(float);
    const size_t smemB = (size_t)(D * VSLICE + 2 * SBUF + 2 * C * ASTR + 8 * PMAT)
                         * sizeof(float);

    cudaFuncSetAttribute(prep_kernel, cudaFuncAttributeMaxDynamicSharedMemorySize,
                         (int)smemA);
    cudaFuncSetAttribute(scan_kernel, cudaFuncAttributeMaxDynamicSharedMemorySize,
                         (int)smemB);

    prep_kernel<<<NC_TOTAL, 256, smemA>>>(q, k, v, beta);
    scan_kernel<<<dim3(NSPLIT, BH), 256, smemB>>>(out);
}